// round 1
// baseline (speedup 1.0000x reference)
#include <cuda_runtime.h>
#include <cstdint>

// QuantizedEmbedding: out[token, :] = dequant(weight[indices[token], :], scales[indices[token], :])
// weight: int32 per packed byte; even = trunc_div(w,16)-8 (high nibble), odd = (w mod 16)-8 (low nibble)
// groupsize 32 floats = 16 packed values; scales per (row, group).

static constexpr int PACKED   = 2048;   // packed int32 per row
static constexpr int NGROUPS  = 128;
static constexpr int DIM      = 4096;
static constexpr int THREADS  = 256;    // 8 packed per thread -> 16 floats out

__device__ __forceinline__ void unpack2(int w, float s, float& e, float& o) {
    // trunc-toward-zero division by 16 (C semantics match torch trunc div)
    int hi = w / 16;
    int lo = w & 15;            // nonnegative mod 16 (two's complement)
    e = (float)(hi - 8) * s;
    o = (float)(lo - 8) * s;
}

__global__ void __launch_bounds__(THREADS, 8)
qemb_kernel(const int* __restrict__ indices,
            const int* __restrict__ weight,
            const float* __restrict__ scales,
            float* __restrict__ out,
            int n_tokens)
{
    int token = blockIdx.x;
    if (token >= n_tokens) return;

    int idx = __ldg(indices + token);
    int t = threadIdx.x;

    // one scale per thread: thread t's 8 packed values all lie in group t/2
    float s = __ldg(scales + (long)idx * NGROUPS + (t >> 1));

    const int4* wrow = reinterpret_cast<const int4*>(weight + (long)idx * PACKED) + t * 2;
    int4 w0 = __ldg(wrow);
    int4 w1 = __ldg(wrow + 1);

    float4 o0, o1, o2, o3;
    unpack2(w0.x, s, o0.x, o0.y);
    unpack2(w0.y, s, o0.z, o0.w);
    unpack2(w0.z, s, o1.x, o1.y);
    unpack2(w0.w, s, o1.z, o1.w);
    unpack2(w1.x, s, o2.x, o2.y);
    unpack2(w1.y, s, o2.z, o2.w);
    unpack2(w1.z, s, o3.x, o3.y);
    unpack2(w1.w, s, o3.z, o3.w);

    float4* orow = reinterpret_cast<float4*>(out + (long)token * DIM) + t * 4;
    orow[0] = o0;
    orow[1] = o1;
    orow[2] = o2;
    orow[3] = o3;
}

extern "C" void kernel_launch(void* const* d_in, const int* in_sizes, int n_in,
                              void* d_out, int out_size)
{
    const int*   indices = (const int*)d_in[0];
    const int*   weight  = (const int*)d_in[1];
    const float* scales  = (const float*)d_in[2];
    float*       out     = (float*)d_out;

    int n_tokens = in_sizes[0];  // 4*4096 = 16384

    qemb_kernel<<<n_tokens, THREADS>>>(indices, weight, scales, out, n_tokens);
}